// round 4
// baseline (speedup 1.0000x reference)
#include <cuda_runtime.h>
#include <math.h>

// Problem constants
#define BB 64
#define TT 128
#define SS 512
#define AA 16
#define OO 4096
#define LOG2PIF 1.8378770664093453f

// ---------------- device global scratch (allocation-free) ----------------
__device__ float g_P[AA * SS * SS];        // transition probabilities [a][s][s']  (16.8 MB)
__device__ float g_E[(TT + 1) * BB * SS];  // emission*action probabilities [t][b][s] (16.9 MB)
__device__ float g_obs_lse[SS];
__device__ float g_pol_lse[SS];
__device__ float g_prior_prob[SS];
__device__ float g_mask[(TT + 1) * BB];    // cumulative-max of dones
__device__ float g_fac[(TT + 1) * BB];     // (1 - was_done) factor per step
__device__ float g_alpha[2 * BB * SS];     // ping-pong forward messages (unnormalized)
__device__ float g_Zpart[2 * 8 * BB];      // per-s'-tile partial normalizers (deterministic)
__device__ float g_logprob[BB];
__device__ int   g_cnt[TT * AA];           // batches-per-action per step
__device__ int   g_list[TT * AA * BB];
__device__ unsigned g_bar_cnt = 0;
__device__ unsigned g_bar_gen = 0;

// ---------------- prep kernels ----------------

// Row-wise logsumexp of obs_logits (512 rows x 4096)
__global__ void k_obs_lse(const float* __restrict__ ol) {
    __shared__ float shm[8];
    __shared__ float bc;
    const int s = blockIdx.x, tid = threadIdx.x;
    const float* row = ol + (size_t)s * OO;
    float mx = -INFINITY;
    for (int i = tid; i < OO; i += 256) mx = fmaxf(mx, row[i]);
    for (int o = 16; o; o >>= 1) mx = fmaxf(mx, __shfl_xor_sync(0xffffffffu, mx, o));
    if ((tid & 31) == 0) shm[tid >> 5] = mx;
    __syncthreads();
    if (tid == 0) { float m = shm[0]; for (int i = 1; i < 8; i++) m = fmaxf(m, shm[i]); bc = m; }
    __syncthreads();
    mx = bc;
    float sm = 0.f;
    for (int i = tid; i < OO; i += 256) sm += expf(row[i] - mx);
    for (int o = 16; o; o >>= 1) sm += __shfl_xor_sync(0xffffffffu, sm, o);
    __syncthreads();
    if ((tid & 31) == 0) shm[tid >> 5] = sm;
    __syncthreads();
    if (tid == 0) { float t = 0.f; for (int i = 0; i < 8; i++) t += shm[i]; g_obs_lse[s] = mx + logf(t); }
}

// Softmax of each transition row -> probabilities in g_P (same layout)
__global__ void k_trans(const float* __restrict__ tl) {
    __shared__ float shm[8];
    __shared__ float bmx, binv;
    const int row = blockIdx.x, tid = threadIdx.x;
    const float* r = tl + (size_t)row * SS;
    float* p = g_P + (size_t)row * SS;
    float x0 = r[tid], x1 = r[tid + 256];
    float mx = fmaxf(x0, x1);
    for (int o = 16; o; o >>= 1) mx = fmaxf(mx, __shfl_xor_sync(0xffffffffu, mx, o));
    if ((tid & 31) == 0) shm[tid >> 5] = mx;
    __syncthreads();
    if (tid == 0) { float m = shm[0]; for (int i = 1; i < 8; i++) m = fmaxf(m, shm[i]); bmx = m; }
    __syncthreads();
    const float e0 = expf(x0 - bmx), e1 = expf(x1 - bmx);
    float sm = e0 + e1;
    for (int o = 16; o; o >>= 1) sm += __shfl_xor_sync(0xffffffffu, sm, o);
    __syncthreads();
    if ((tid & 31) == 0) shm[tid >> 5] = sm;
    __syncthreads();
    if (tid == 0) { float t = 0.f; for (int i = 0; i < 8; i++) t += shm[i]; binv = 1.0f / t; }
    __syncthreads();
    p[tid] = e0 * binv;
    p[tid + 256] = e1 * binv;
}

// policy row lse (over 16) + prior softmax (over 512). 1 block x 512 threads.
__global__ void k_pol_prior(const float* __restrict__ pl, const float* __restrict__ prl) {
    __shared__ float shm[16];
    __shared__ float bmx, bsm;
    const int s = threadIdx.x;
    float mx = -INFINITY;
#pragma unroll
    for (int a = 0; a < AA; a++) mx = fmaxf(mx, pl[s * AA + a]);
    float sm = 0.f;
#pragma unroll
    for (int a = 0; a < AA; a++) sm += expf(pl[s * AA + a] - mx);
    g_pol_lse[s] = mx + logf(sm);

    const float pv = prl[s];
    float v = pv;
    for (int o = 16; o; o >>= 1) v = fmaxf(v, __shfl_xor_sync(0xffffffffu, v, o));
    if ((s & 31) == 0) shm[s >> 5] = v;
    __syncthreads();
    if (s == 0) { float m = shm[0]; for (int i = 1; i < 16; i++) m = fmaxf(m, shm[i]); bmx = m; }
    __syncthreads();
    const float e = expf(pv - bmx);
    float w = e;
    for (int o = 16; o; o >>= 1) w += __shfl_xor_sync(0xffffffffu, w, o);
    __syncthreads();
    if ((s & 31) == 0) shm[s >> 5] = w;
    __syncthreads();
    if (s == 0) { float t = 0.f; for (int i = 0; i < 16; i++) t += shm[i]; bsm = t; }
    __syncthreads();
    g_prior_prob[s] = e / bsm;
}

// cumulative-max of dones and the (1 - was_done) factors. 1 block x 64 threads.
__global__ void k_cm(const float* __restrict__ dones) {
    const int b = threadIdx.x;
    if (b < BB) {
        float prev = 0.f, cm = 0.f;
        for (int t = 0; t <= TT; t++) {
            cm = fmaxf(cm, dones[t * BB + b]);
            g_mask[t * BB + b] = cm;
            g_fac[t * BB + b] = (t == 0) ? 1.0f : (1.0f - prev);
            prev = cm;
        }
    }
}

// group batches by action for each step. 1 block x 128 threads.
__global__ void k_lists(const int* __restrict__ actions) {
    const int t = threadIdx.x;
    if (t < TT) {
        int c[AA];
#pragma unroll
        for (int i = 0; i < AA; i++) c[i] = 0;
        for (int b = 0; b < BB; b++) {
            const int a = actions[t * BB + b];
            g_list[(t * AA + a) * BB + c[a]] = b;
            c[a]++;
        }
#pragma unroll
        for (int i = 0; i < AA; i++) g_cnt[t * AA + i] = c[i];
    }
}

// emission * action probabilities E[t][b][s] = exp(log_obs + log_reward + log_act)
__global__ void k_E(const int* __restrict__ obs, const float* __restrict__ rewards,
                    const int* __restrict__ actions, const float* __restrict__ regime,
                    const float* __restrict__ obs_logits, const float* __restrict__ policy_logits,
                    const float* __restrict__ r_mu, const float* __restrict__ r_logsig) {
    const int tb = blockIdx.x;
    const int t = tb >> 6, b = tb & 63;
    const int s = threadIdx.x;
    const int o = obs[t * BB + b];
    const float r = rewards[t * BB + b];
    const float lo = obs_logits[(size_t)s * OO + o] - g_obs_lse[s];
    const float isig = expf(-r_logsig[s]);
    const float d = (r - r_mu[s]) * isig;
    const float lr = -0.5f * d * d - r_logsig[s] - 0.5f * LOG2PIF;
    float la = 0.f;
    if (t < TT) {
        const int aa = actions[t * BB + b];
        const bool off = (g_mask[t * BB + b] == 1.0f) || (regime[b] == 1.0f);
        if (!off) la = policy_logits[s * AA + aa] - g_pol_lse[s];
    }
    g_E[(size_t)tb * SS + s] = expf(lo + lr + la);
}

// alpha_0 = prior_prob * E_0 ; Z_0 into tile-0 partial slot; zero the rest; zero logprob.
__global__ void k_init() {
    __shared__ float shm[8];
    const int b = blockIdx.x, tid = threadIdx.x;
    float sm = 0.f;
    for (int s = tid; s < SS; s += 256) {
        const float v = g_prior_prob[s] * g_E[(size_t)b * SS + s];  // t=0 slice
        g_alpha[b * SS + s] = v;                                    // buffer 0
        sm += v;
    }
    for (int o = 16; o; o >>= 1) sm += __shfl_xor_sync(0xffffffffu, sm, o);
    if ((tid & 31) == 0) shm[tid >> 5] = sm;
    __syncthreads();
    if (tid == 0) {
        float t = 0.f;
        for (int i = 0; i < 8; i++) t += shm[i];
        g_Zpart[0 * 512 + 0 * BB + b] = t;
        g_logprob[b] = 0.f;
    }
    if (tid >= 1 && tid < 8) g_Zpart[0 * 512 + tid * BB + b] = 0.f;
}

// ---------------- main persistent cooperative kernel ----------------

__device__ __forceinline__ void grid_barrier(int nblocks) {
    __threadfence();
    __syncthreads();
    if (threadIdx.x == 0) {
        const unsigned g = *(volatile unsigned*)&g_bar_gen;
        const unsigned t = atomicAdd(&g_bar_cnt, 1u);
        if (t == (unsigned)(nblocks - 1)) {
            atomicExch(&g_bar_cnt, 0u);
            __threadfence();
            *(volatile unsigned*)&g_bar_gen = g + 1u;
        } else {
            while (*(volatile unsigned*)&g_bar_gen == g) { }
        }
        __threadfence();
    }
    __syncthreads();
}

// grid: 128 blocks = 16 actions x 8 s'-tiles of 64 ; block: 256 threads = 64 ss x 4 kq
__global__ void __launch_bounds__(256) k_forward(float* __restrict__ out) {
    __shared__ float sal[SS][8];        // alpha for up to 8 member batches, [k][m]
    __shared__ float red[4][64][8];     // kq partial accumulators
    __shared__ float sinvZ[8];
    __shared__ int   slist[8];
    __shared__ float zred[2][8];

    const int tid = threadIdx.x, ss = tid & 63, kq = tid >> 6;
    const int a = blockIdx.x >> 3, tile = blockIdx.x & 7, s0 = tile << 6;
    const float* __restrict__ Pa = g_P + ((size_t)a << 18) + s0 + ss;

    for (int t = 1; t <= TT; t++) {
        const int prev = (t - 1) & 1, cur = t & 1, at = t - 1;
        const int n = g_cnt[at * AA + a];

        // log accumulation for Z_{t-1} (exactly once per batch: tile 0 of its action)
        if (tile == 0 && tid < n) {
            const int b = g_list[(at * AA + a) * BB + tid];
            float Z = 0.f;
#pragma unroll
            for (int k2 = 0; k2 < 8; k2++) Z += __ldcg(&g_Zpart[prev * 512 + k2 * BB + b]);
            g_logprob[b] = __ldcg(&g_logprob[b]) + logf(Z) * g_fac[at * BB + b];
        }

        for (int c0 = 0; c0 < n; c0 += 8) {
            const int M = min(8, n - c0);
            if (tid < 8) {
                int b = -1;
                float iz = 0.f;
                if (tid < M) {
                    b = g_list[(at * AA + a) * BB + c0 + tid];
                    float Z = 0.f;
#pragma unroll
                    for (int k2 = 0; k2 < 8; k2++) Z += __ldcg(&g_Zpart[prev * 512 + k2 * BB + b]);
                    iz = 1.0f / Z;
                }
                slist[tid] = b;
                sinvZ[tid] = iz;
            }
            __syncthreads();

            // stage normalized alpha vectors into smem
            for (int k = tid; k < SS; k += 256) {
#pragma unroll
                for (int m = 0; m < 8; m++) {
                    const int b = slist[m];
                    sal[k][m] = (b >= 0) ? __ldcg(&g_alpha[prev * BB * SS + b * SS + k]) * sinvZ[m] : 0.0f;
                }
            }
            __syncthreads();

            // matvec chunk: this thread covers column s0+ss over k in [kq*128, kq*128+128)
            float a0 = 0, a1 = 0, a2 = 0, a3 = 0, a4 = 0, a5 = 0, a6 = 0, a7 = 0;
            const int kb = kq << 7;
#pragma unroll 8
            for (int k = 0; k < 128; k++) {
                const float w = Pa[(size_t)(kb + k) << 9];
                const float4 v0 = *(const float4*)&sal[kb + k][0];
                const float4 v1 = *(const float4*)&sal[kb + k][4];
                a0 += w * v0.x; a1 += w * v0.y; a2 += w * v0.z; a3 += w * v0.w;
                a4 += w * v1.x; a5 += w * v1.y; a6 += w * v1.z; a7 += w * v1.w;
            }
            *(float4*)&red[kq][ss][0] = make_float4(a0, a1, a2, a3);
            *(float4*)&red[kq][ss][4] = make_float4(a4, a5, a6, a7);
            __syncthreads();

            if (kq == 0) {
                float gsum[8];
                {
                    float4 x0 = *(const float4*)&red[0][ss][0];
                    float4 x1 = *(const float4*)&red[1][ss][0];
                    float4 x2 = *(const float4*)&red[2][ss][0];
                    float4 x3 = *(const float4*)&red[3][ss][0];
                    gsum[0] = x0.x + x1.x + x2.x + x3.x;
                    gsum[1] = x0.y + x1.y + x2.y + x3.y;
                    gsum[2] = x0.z + x1.z + x2.z + x3.z;
                    gsum[3] = x0.w + x1.w + x2.w + x3.w;
                    x0 = *(const float4*)&red[0][ss][4];
                    x1 = *(const float4*)&red[1][ss][4];
                    x2 = *(const float4*)&red[2][ss][4];
                    x3 = *(const float4*)&red[3][ss][4];
                    gsum[4] = x0.x + x1.x + x2.x + x3.x;
                    gsum[5] = x0.y + x1.y + x2.y + x3.y;
                    gsum[6] = x0.z + x1.z + x2.z + x3.z;
                    gsum[7] = x0.w + x1.w + x2.w + x3.w;
                }
#pragma unroll
                for (int m = 0; m < 8; m++) {
                    const int b = slist[m];
                    float gamma = 0.f;
                    if (b >= 0) {
                        gamma = gsum[m] * g_E[((size_t)t * BB + b) * SS + s0 + ss];
                        g_alpha[cur * BB * SS + b * SS + s0 + ss] = gamma;
                    }
                    float v = gamma;
#pragma unroll
                    for (int o = 16; o; o >>= 1) v += __shfl_xor_sync(0xffffffffu, v, o);
                    if ((ss & 31) == 0) zred[ss >> 5][m] = v;
                }
            }
            __syncthreads();
            if (tid < M) {
                const int b = slist[tid];
                g_Zpart[cur * 512 + tile * BB + b] = zred[0][tid] + zred[1][tid];
            }
            __syncthreads();
        }
        grid_barrier(128);
    }

    // final: add log Z_T (buffer parity of t=128 is 0) and emit
    if (blockIdx.x == 0 && tid < BB) {
        float Z = 0.f;
#pragma unroll
        for (int k2 = 0; k2 < 8; k2++) Z += __ldcg(&g_Zpart[0 * 512 + k2 * BB + tid]);
        out[tid] = __ldcg(&g_logprob[tid]) + logf(Z) * g_fac[TT * BB + tid];
    }
}

// ---------------- launch ----------------
extern "C" void kernel_launch(void* const* d_in, const int* in_sizes, int n_in,
                              void* d_out, int out_size) {
    const float* regime        = (const float*)d_in[0];
    const int*   obs           = (const int*)d_in[1];
    const float* rewards       = (const float*)d_in[2];
    const float* dones         = (const float*)d_in[3];
    const int*   actions       = (const int*)d_in[4];
    const float* prior_logits  = (const float*)d_in[5];
    const float* trans_logits  = (const float*)d_in[6];
    const float* obs_logits    = (const float*)d_in[7];
    const float* policy_logits = (const float*)d_in[8];
    const float* r_mu          = (const float*)d_in[9];
    const float* r_logsig      = (const float*)d_in[10];
    float* out = (float*)d_out;

    k_obs_lse<<<SS, 256>>>(obs_logits);
    k_trans<<<AA * SS, 256>>>(trans_logits);
    k_pol_prior<<<1, 512>>>(policy_logits, prior_logits);
    k_cm<<<1, 64>>>(dones);
    k_lists<<<1, 128>>>(actions);
    k_E<<<(TT + 1) * BB, 512>>>(obs, rewards, actions, regime,
                                obs_logits, policy_logits, r_mu, r_logsig);
    k_init<<<BB, 256>>>();
    k_forward<<<128, 256>>>(out);
}

// round 5
// speedup vs baseline: 1.3877x; 1.3877x over previous
#include <cuda_runtime.h>
#include <math.h>

// Problem constants
#define BB 64
#define TT 128
#define SS 512
#define AA 16
#define OO 4096
#define LOG2PIF 1.8378770664093453f

// ---------------- device global scratch (allocation-free) ----------------
__device__ float g_P[AA * SS * SS];        // transition probabilities [a][s][s']
__device__ float g_E[(TT + 1) * BB * SS];  // emission*action probabilities [t][b][s]
__device__ float g_obs_lse[SS];
__device__ float g_pol_lse[SS];
__device__ float g_prior_prob[SS];
__device__ float g_mask[(TT + 1) * BB];
__device__ float g_fac[(TT + 1) * BB];
__device__ float g_alpha[2 * BB * SS];
__device__ float g_Zpart[2 * 8 * BB];
__device__ float g_logprob[BB];
__device__ int   g_cnt[TT * AA];
__device__ int   g_list[TT * AA * BB];
__device__ unsigned g_bar_cnt = 0;
__device__ unsigned g_bar_gen = 0;

// ---------------- fused prep kernel #1 ----------------
// blocks 0..511 : row-wise logsumexp of obs_logits (512 threads)
// block 512     : policy row lse + prior softmax
// block 513     : cumulative-max of dones + factors
// block 514     : per-step action lists
__global__ void __launch_bounds__(512) k_prep(const float* __restrict__ ol,
                                              const float* __restrict__ pl,
                                              const float* __restrict__ prl,
                                              const float* __restrict__ dones,
                                              const int* __restrict__ actions) {
    __shared__ float shm[16];
    __shared__ float bc;
    const int tid = threadIdx.x;
    const int blk = blockIdx.x;

    if (blk < SS) {
        const float* row = ol + (size_t)blk * OO;
        float mx = -INFINITY;
        for (int i = tid; i < OO; i += 512) mx = fmaxf(mx, row[i]);
        for (int o = 16; o; o >>= 1) mx = fmaxf(mx, __shfl_xor_sync(0xffffffffu, mx, o));
        if ((tid & 31) == 0) shm[tid >> 5] = mx;
        __syncthreads();
        if (tid == 0) { float m = shm[0]; for (int i = 1; i < 16; i++) m = fmaxf(m, shm[i]); bc = m; }
        __syncthreads();
        mx = bc;
        float sm = 0.f;
        for (int i = tid; i < OO; i += 512) sm += expf(row[i] - mx);
        for (int o = 16; o; o >>= 1) sm += __shfl_xor_sync(0xffffffffu, sm, o);
        __syncthreads();
        if ((tid & 31) == 0) shm[tid >> 5] = sm;
        __syncthreads();
        if (tid == 0) { float t = 0.f; for (int i = 0; i < 16; i++) t += shm[i]; g_obs_lse[blk] = mx + logf(t); }
    } else if (blk == SS) {
        __shared__ float bmx, bsm;
        const int s = tid;  // 512 threads
        float mx = -INFINITY;
#pragma unroll
        for (int a = 0; a < AA; a++) mx = fmaxf(mx, pl[s * AA + a]);
        float sm = 0.f;
#pragma unroll
        for (int a = 0; a < AA; a++) sm += expf(pl[s * AA + a] - mx);
        g_pol_lse[s] = mx + logf(sm);

        const float pv = prl[s];
        float v = pv;
        for (int o = 16; o; o >>= 1) v = fmaxf(v, __shfl_xor_sync(0xffffffffu, v, o));
        if ((s & 31) == 0) shm[s >> 5] = v;
        __syncthreads();
        if (s == 0) { float m = shm[0]; for (int i = 1; i < 16; i++) m = fmaxf(m, shm[i]); bmx = m; }
        __syncthreads();
        const float e = expf(pv - bmx);
        float w = e;
        for (int o = 16; o; o >>= 1) w += __shfl_xor_sync(0xffffffffu, w, o);
        __syncthreads();
        if ((s & 31) == 0) shm[s >> 5] = w;
        __syncthreads();
        if (s == 0) { float t = 0.f; for (int i = 0; i < 16; i++) t += shm[i]; bsm = t; }
        __syncthreads();
        g_prior_prob[s] = e / bsm;
    } else if (blk == SS + 1) {
        const int b = tid;
        if (b < BB) {
            float prev = 0.f, cm = 0.f;
            for (int t = 0; t <= TT; t++) {
                cm = fmaxf(cm, dones[t * BB + b]);
                g_mask[t * BB + b] = cm;
                g_fac[t * BB + b] = (t == 0) ? 1.0f : (1.0f - prev);
                prev = cm;
            }
        }
    } else {
        const int t = tid;
        if (t < TT) {
            int c[AA];
#pragma unroll
            for (int i = 0; i < AA; i++) c[i] = 0;
            for (int b = 0; b < BB; b++) {
                const int a = actions[t * BB + b];
                g_list[(t * AA + a) * BB + c[a]] = b;
                c[a]++;
            }
#pragma unroll
            for (int i = 0; i < AA; i++) g_cnt[t * AA + i] = c[i];
        }
    }
}

// ---------------- prep kernel #2: transition softmax ----------------
__global__ void k_trans(const float* __restrict__ tl) {
    __shared__ float shm[8];
    __shared__ float bmx, binv;
    const int row = blockIdx.x, tid = threadIdx.x;
    const float* r = tl + (size_t)row * SS;
    float* p = g_P + (size_t)row * SS;
    float x0 = r[tid], x1 = r[tid + 256];
    float mx = fmaxf(x0, x1);
    for (int o = 16; o; o >>= 1) mx = fmaxf(mx, __shfl_xor_sync(0xffffffffu, mx, o));
    if ((tid & 31) == 0) shm[tid >> 5] = mx;
    __syncthreads();
    if (tid == 0) { float m = shm[0]; for (int i = 1; i < 8; i++) m = fmaxf(m, shm[i]); bmx = m; }
    __syncthreads();
    const float e0 = expf(x0 - bmx), e1 = expf(x1 - bmx);
    float sm = e0 + e1;
    for (int o = 16; o; o >>= 1) sm += __shfl_xor_sync(0xffffffffu, sm, o);
    __syncthreads();
    if ((tid & 31) == 0) shm[tid >> 5] = sm;
    __syncthreads();
    if (tid == 0) { float t = 0.f; for (int i = 0; i < 8; i++) t += shm[i]; binv = 1.0f / t; }
    __syncthreads();
    p[tid] = e0 * binv;
    p[tid + 256] = e1 * binv;
}

// ---------------- prep kernel #3: emission*action probabilities ----------------
__global__ void __launch_bounds__(512) k_E(const int* __restrict__ obs, const float* __restrict__ rewards,
                    const int* __restrict__ actions, const float* __restrict__ regime,
                    const float* __restrict__ obs_logits, const float* __restrict__ policy_logits,
                    const float* __restrict__ r_mu, const float* __restrict__ r_logsig) {
    const int tb = blockIdx.x;
    const int t = tb >> 6, b = tb & 63;
    const int s = threadIdx.x;
    const int o = obs[t * BB + b];
    const float r = rewards[t * BB + b];
    const float lo = obs_logits[(size_t)s * OO + o] - g_obs_lse[s];
    const float isig = expf(-r_logsig[s]);
    const float d = (r - r_mu[s]) * isig;
    const float lr = -0.5f * d * d - r_logsig[s] - 0.5f * LOG2PIF;
    float la = 0.f;
    if (t < TT) {
        const int aa = actions[t * BB + b];
        const bool off = (g_mask[t * BB + b] == 1.0f) || (regime[b] == 1.0f);
        if (!off) la = policy_logits[s * AA + aa] - g_pol_lse[s];
    }
    g_E[(size_t)tb * SS + s] = expf(lo + lr + la);
}

// ---------------- main persistent cooperative kernel ----------------

__device__ __forceinline__ void grid_barrier(int nblocks) {
    __threadfence();
    __syncthreads();
    if (threadIdx.x == 0) {
        const unsigned g = *(volatile unsigned*)&g_bar_gen;
        const unsigned t = atomicAdd(&g_bar_cnt, 1u);
        if (t == (unsigned)(nblocks - 1)) {
            atomicExch(&g_bar_cnt, 0u);
            __threadfence();
            *(volatile unsigned*)&g_bar_gen = g + 1u;
        } else {
            while (*(volatile unsigned*)&g_bar_gen == g) { }
        }
        __threadfence();
    }
    __syncthreads();
}

// SMEM layout (dynamic):
//   sp [512][64]   P slice            131072 B
//   sal[512][8]    staged alphas       16384 B
//   red[4][64][8]  kq partials          8192 B
//   misc: sinvZ(8f) slist(8i) zred[2][8] zz(8f)
#define SMEM_SP   0
#define SMEM_SAL  131072
#define SMEM_RED  147456
#define SMEM_MISC 155648
#define SMEM_TOTAL (155648 + 256)

// grid: 128 blocks = 16 actions x 8 s'-tiles of 64 ; block: 256 threads = 64 ss x 4 kq
__global__ void __launch_bounds__(256) k_forward(float* __restrict__ out) {
    extern __shared__ char smem[];
    float (* __restrict__ sp)[64]     = (float(*)[64])(smem + SMEM_SP);
    float (* __restrict__ sal)[8]     = (float(*)[8])(smem + SMEM_SAL);
    float (* __restrict__ red)[64][8] = (float(*)[64][8])(smem + SMEM_RED);
    float* sinvZ = (float*)(smem + SMEM_MISC);
    int*   slist = (int*)(smem + SMEM_MISC + 32);
    float (*zred)[8] = (float(*)[8])(smem + SMEM_MISC + 64);
    float* zz    = (float*)(smem + SMEM_MISC + 128);

    const int tid = threadIdx.x, ss = tid & 63, kq = tid >> 6;
    const int a = blockIdx.x >> 3, tile = blockIdx.x & 7, s0 = tile << 6;

    // ---- fused init (was k_init): blocks (2b, 2b+1) initialize batch b ----
    {
        const int b = blockIdx.x >> 1, half = blockIdx.x & 1;
        const int col = (half << 8) + tid;
        const float v = g_prior_prob[col] * __ldcg(&g_E[b * SS + col]);
        __stcg(&g_alpha[b * SS + col], v);
        float w = v;
#pragma unroll
        for (int o = 16; o; o >>= 1) w += __shfl_xor_sync(0xffffffffu, w, o);
        if ((tid & 31) == 0) zz[tid >> 5] = w;
        __syncthreads();
        if (tid < 4)
            __stcg(&g_Zpart[0 * 512 + ((half << 2) + tid) * BB + b], zz[2 * tid] + zz[2 * tid + 1]);
        if (tid == 0 && half == 0) __stcg(&g_logprob[b], 0.f);
    }

    // ---- stage this block's P slice into SMEM (once, reused for all 128 steps) ----
    {
        const float* __restrict__ src = g_P + ((size_t)a << 18) + s0;
        for (int i = tid; i < SS * 64; i += 256) {
            const int k = i >> 6, c = i & 63;
            sp[k][c] = src[((size_t)k << 9) + c];
        }
    }
    grid_barrier(128);

    for (int t = 1; t <= TT; t++) {
        const int prev = (t - 1) & 1, cur = t & 1, at = t - 1;
        const int n = g_cnt[at * AA + a];

        // log accumulation for Z_{t-1} (once per batch: tile 0 of its action)
        if (tile == 0 && tid < n) {
            const int b = g_list[(at * AA + a) * BB + tid];
            float Z = 0.f;
#pragma unroll
            for (int k2 = 0; k2 < 8; k2++) Z += __ldcg(&g_Zpart[prev * 512 + k2 * BB + b]);
            __stcg(&g_logprob[b], __ldcg(&g_logprob[b]) + logf(Z) * g_fac[at * BB + b]);
        }

        for (int c0 = 0; c0 < n; c0 += 8) {
            const int M = min(8, n - c0);
            if (tid < 8) {
                int b = -1;
                float iz = 0.f;
                if (tid < M) {
                    b = g_list[(at * AA + a) * BB + c0 + tid];
                    float Z = 0.f;
#pragma unroll
                    for (int k2 = 0; k2 < 8; k2++) Z += __ldcg(&g_Zpart[prev * 512 + k2 * BB + b]);
                    iz = 1.0f / Z;
                }
                slist[tid] = b;
                sinvZ[tid] = iz;
            }
            __syncthreads();

            // stage normalized alpha vectors into smem
            for (int k = tid; k < SS; k += 256) {
#pragma unroll
                for (int m = 0; m < 8; m++) {
                    const int b = slist[m];
                    sal[k][m] = (b >= 0) ? __ldcg(&g_alpha[prev * BB * SS + b * SS + k]) * sinvZ[m] : 0.0f;
                }
            }
            __syncthreads();

            // matvec chunk with f32x2 FMA: column s0+ss, k in [kq*128, kq*128+128)
            const int kb = kq << 7;
            unsigned long long acc01 = 0ull, acc23 = 0ull, acc45 = 0ull, acc67 = 0ull;
#pragma unroll 4
            for (int k = 0; k < 128; k++) {
                const float w = sp[kb + k][ss];
                unsigned long long ww;
                asm("mov.b64 %0, {%1, %1};" : "=l"(ww) : "f"(w));
                union { float4 f4; unsigned long long u[2]; } u0, u1;
                u0.f4 = *(const float4*)&sal[kb + k][0];
                u1.f4 = *(const float4*)&sal[kb + k][4];
                asm("fma.rn.f32x2 %0, %1, %2, %0;" : "+l"(acc01) : "l"(ww), "l"(u0.u[0]));
                asm("fma.rn.f32x2 %0, %1, %2, %0;" : "+l"(acc23) : "l"(ww), "l"(u0.u[1]));
                asm("fma.rn.f32x2 %0, %1, %2, %0;" : "+l"(acc45) : "l"(ww), "l"(u1.u[0]));
                asm("fma.rn.f32x2 %0, %1, %2, %0;" : "+l"(acc67) : "l"(ww), "l"(u1.u[1]));
            }
            {
                float a0, a1, a2, a3, a4, a5, a6, a7;
                asm("mov.b64 {%0, %1}, %2;" : "=f"(a0), "=f"(a1) : "l"(acc01));
                asm("mov.b64 {%0, %1}, %2;" : "=f"(a2), "=f"(a3) : "l"(acc23));
                asm("mov.b64 {%0, %1}, %2;" : "=f"(a4), "=f"(a5) : "l"(acc45));
                asm("mov.b64 {%0, %1}, %2;" : "=f"(a6), "=f"(a7) : "l"(acc67));
                *(float4*)&red[kq][ss][0] = make_float4(a0, a1, a2, a3);
                *(float4*)&red[kq][ss][4] = make_float4(a4, a5, a6, a7);
            }
            __syncthreads();

            if (kq == 0) {
                float gsum[8];
                {
                    float4 x0 = *(const float4*)&red[0][ss][0];
                    float4 x1 = *(const float4*)&red[1][ss][0];
                    float4 x2 = *(const float4*)&red[2][ss][0];
                    float4 x3 = *(const float4*)&red[3][ss][0];
                    gsum[0] = x0.x + x1.x + x2.x + x3.x;
                    gsum[1] = x0.y + x1.y + x2.y + x3.y;
                    gsum[2] = x0.z + x1.z + x2.z + x3.z;
                    gsum[3] = x0.w + x1.w + x2.w + x3.w;
                    x0 = *(const float4*)&red[0][ss][4];
                    x1 = *(const float4*)&red[1][ss][4];
                    x2 = *(const float4*)&red[2][ss][4];
                    x3 = *(const float4*)&red[3][ss][4];
                    gsum[4] = x0.x + x1.x + x2.x + x3.x;
                    gsum[5] = x0.y + x1.y + x2.y + x3.y;
                    gsum[6] = x0.z + x1.z + x2.z + x3.z;
                    gsum[7] = x0.w + x1.w + x2.w + x3.w;
                }
#pragma unroll
                for (int m = 0; m < 8; m++) {
                    const int b = slist[m];
                    float gamma = 0.f;
                    if (b >= 0) {
                        gamma = gsum[m] * __ldcg(&g_E[((size_t)t * BB + b) * SS + s0 + ss]);
                        __stcg(&g_alpha[cur * BB * SS + b * SS + s0 + ss], gamma);
                    }
                    float v = gamma;
#pragma unroll
                    for (int o = 16; o; o >>= 1) v += __shfl_xor_sync(0xffffffffu, v, o);
                    if ((ss & 31) == 0) zred[ss >> 5][m] = v;
                }
            }
            __syncthreads();
            if (tid < M) {
                const int b = slist[tid];
                __stcg(&g_Zpart[cur * 512 + tile * BB + b], zred[0][tid] + zred[1][tid]);
            }
            __syncthreads();
        }
        grid_barrier(128);
    }

    // final: add log Z_T (buffer parity of t=128 is 0) and emit
    if (blockIdx.x == 0 && tid < BB) {
        float Z = 0.f;
#pragma unroll
        for (int k2 = 0; k2 < 8; k2++) Z += __ldcg(&g_Zpart[0 * 512 + k2 * BB + tid]);
        out[tid] = __ldcg(&g_logprob[tid]) + logf(Z) * g_fac[TT * BB + tid];
    }
}

// ---------------- launch ----------------
extern "C" void kernel_launch(void* const* d_in, const int* in_sizes, int n_in,
                              void* d_out, int out_size) {
    const float* regime        = (const float*)d_in[0];
    const int*   obs           = (const int*)d_in[1];
    const float* rewards       = (const float*)d_in[2];
    const float* dones         = (const float*)d_in[3];
    const int*   actions       = (const int*)d_in[4];
    const float* prior_logits  = (const float*)d_in[5];
    const float* trans_logits  = (const float*)d_in[6];
    const float* obs_logits    = (const float*)d_in[7];
    const float* policy_logits = (const float*)d_in[8];
    const float* r_mu          = (const float*)d_in[9];
    const float* r_logsig      = (const float*)d_in[10];
    float* out = (float*)d_out;

    static int smem_set = 0;
    if (!smem_set) {
        cudaFuncSetAttribute(k_forward, cudaFuncAttributeMaxDynamicSharedMemorySize, SMEM_TOTAL);
        smem_set = 1;
    }

    k_prep<<<SS + 3, 512>>>(obs_logits, policy_logits, prior_logits, dones, actions);
    k_trans<<<AA * SS, 256>>>(trans_logits);
    k_E<<<(TT + 1) * BB, 512>>>(obs, rewards, actions, regime,
                                obs_logits, policy_logits, r_mu, r_logsig);
    k_forward<<<128, 256, SMEM_TOTAL>>>(out);
}